// round 11
// baseline (speedup 1.0000x reference)
#include <cuda_runtime.h>

// Problem constants (fixed by setup_inputs)
#define Bq      128
#define Nq      8192
#define THREADS 768
#define WARPS   24

#define LOG2E 1.4426950408889634f

typedef unsigned long long ull;

// ---- Blackwell packed fp32x2 helpers (FFMA2 only reachable via PTX) ----
static __device__ __forceinline__ ull pk2(float lo, float hi) {
    ull r; asm("mov.b64 %0, {%1, %2};" : "=l"(r) : "f"(lo), "f"(hi)); return r;
}
static __device__ __forceinline__ ull ffma2(ull a, ull b, ull c) {
    ull d; asm("fma.rn.f32x2 %0, %1, %2, %3;" : "=l"(d) : "l"(a), "l"(b), "l"(c)); return d;
}
static __device__ __forceinline__ float2 upk2(ull v) {
    float2 f; asm("mov.b64 {%0, %1}, %2;" : "=f"(f.x), "=f"(f.y) : "l"(v)); return f;
}
static __device__ __forceinline__ ull relu2(ull v) {
    float2 f = upk2(v);
    return pk2(fmaxf(f.x, 0.f), fmaxf(f.y, 0.f));
}

__global__ __launch_bounds__(THREADS, 1)
void mha_fused_kernel(const float* __restrict__ radar_xy,
                      const float* __restrict__ radar_dir,
                      const float* __restrict__ pts,
                      const float* __restrict__ enc_w1,
                      const float* __restrict__ enc_b1,
                      const float* __restrict__ enc_w2,
                      const float* __restrict__ enc_b2,
                      const float* __restrict__ sc_w1,
                      const float* __restrict__ sc_b1,
                      const float* __restrict__ sc_w2,
                      const float* __restrict__ sc_b2,
                      const float* __restrict__ out_w1,
                      const float* __restrict__ out_b1,
                      const float* __restrict__ out_w2,
                      const float* __restrict__ out_b2,
                      float* __restrict__ out)
{
    // Staging areas (read once into registers, then untouched in the hot loop)
    __shared__ ulonglong2 sAB[4][32];                // (a-pair px, b-pair py)
    __shared__ ulonglong2 sCV[4][32];                // (c-pair bias, v-pair w2)
    __shared__ ull        sE1p[32], sE2p[32], sBEp[32];
    // Softmax-weight broadcast, duplicated pairs: per (buf, warp, pt): (h0,h0,h1,h1),(h2,h2,h3,h3)
    __shared__ float4     sWexp[2][WARPS][8];
    __shared__ float      sRed[WARPS][4][64];
    __shared__ float      sWsum[WARPS][4];
    __shared__ float      sSum[4];
    __shared__ float      sPooled[4][64];
    __shared__ float      sCtx[256];
    __shared__ float      sO[64];

    const int b    = blockIdx.x;
    const int tid  = threadIdx.x;
    const int warp = tid >> 5;
    const int lane = tid & 31;

    const float r0 = radar_xy[b*2+0], r1 = radar_xy[b*2+1];
    const float r2 = radar_dir[b*2+0], r3 = radar_dir[b*2+1];

    // ---------------- Staging ----------------
    if (tid < 128) {
        const int k = tid >> 5, hs = tid & 31;
        const int hh = hs >> 3, j = (hs & 7) * 8 + k * 2;
        const float* w = sc_w1 + (size_t)hh * 384;
        const float c0 = sc_b1[hh*64+j]   + r0*w[j]   + r1*w[64+j]   + r2*w[128+j]   + r3*w[192+j];
        const float c1 = sc_b1[hh*64+j+1] + r0*w[j+1] + r1*w[64+j+1] + r2*w[128+j+1] + r3*w[192+j+1];
        ulonglong2 cv;
        cv.x = pk2(c0, c1);
        cv.y = pk2(sc_w2[hh*64+j], sc_w2[hh*64+j+1]);
        sCV[k][hs] = cv;
    } else if (tid < 224) {
        const int idx = tid - 128, arr = idx >> 5, l = idx & 31;
        if (arr == 0)      sE1p[l] = pk2(enc_w1[256+l], enc_w1[256+l+32]);
        else if (arr == 1) sE2p[l] = pk2(enc_w1[320+l], enc_w1[320+l+32]);
        else {
            const float b0 = enc_b1[l]    + r0*enc_w1[l]     + r1*enc_w1[64+l]
                                          + r2*enc_w1[128+l]  + r3*enc_w1[192+l];
            const float b1 = enc_b1[l+32] + r0*enc_w1[l+32]  + r1*enc_w1[64+l+32]
                                          + r2*enc_w1[128+l+32] + r3*enc_w1[192+l+32];
            sBEp[l] = pk2(b0, b1);
        }
    } else if (tid >= 256 && tid < 384) {
        const int idx = tid - 256;
        const int k = idx >> 5, hs = idx & 31;
        const int hh = hs >> 3, j = (hs & 7) * 8 + k * 2;
        const float* w = sc_w1 + (size_t)hh * 384;
        ulonglong2 ab;
        ab.x = pk2(w[256+j], w[256+j+1]);   // row 4: px coeffs
        ab.y = pk2(w[320+j], w[320+j+1]);   // row 5: py coeffs
        sAB[k][hs] = ab;
    }
    __syncthreads();

    // ---------------- Per-lane constants (all register-resident) ----------------
    const int h = lane >> 3, s = lane & 7;
    const float b2l = sc_b2[h] * LOG2E;
    // After the butterfly, lane s holds point p(s) = (s&1)*2 + ((s>>1)&1)
    const int pOwn = ((s & 1) << 1) + ((s >> 1) & 1);
    const bool sel1 = (s & 1) != 0, sel2 = (s & 2) != 0;

    ull aK[4], bK[4], cK[4], vK[4];
    #pragma unroll
    for (int k = 0; k < 4; k++) {
        ulonglong2 t = sAB[k][lane]; aK[k] = t.x; bK[k] = t.y;
        ulonglong2 u = sCV[k][lane]; cK[k] = u.x; vK[k] = u.y;
    }
    const ull e1p = sE1p[lane], e2p = sE2p[lane], bep = sBEp[lane];

    ull P0 = 0ull, P1 = 0ull, P2 = 0ull, P3 = 0ull;   // pooled (feat lane, lane+32) x 4 heads
    float sOwn = 0.f;

    // Point split: warps 0..7 own 344 pts, warps 8..23 own 340 pts (all /4)
    const int nb    = (warp < 8) ? 86 : 85;
    const int start = (warp < 8) ? warp * 344 : 2752 + (warp - 8) * 340;
    const float4* P4 = reinterpret_cast<const float4*>(pts) + ((size_t)b * 4096 + (start >> 1));

    // Write slot for this lane's (pt, h) softmax weight (duplicated pair), buf 0
    float2* wptr = reinterpret_cast<float2*>(
        reinterpret_cast<float*>(&sWexp[0][warp][0]) + pOwn * 8 + h * 2);
    const ulonglong2* WV = reinterpret_cast<const ulonglong2*>(&sWexp[0][warp][0]);
    const int bufStrF2 = WARPS * 16;   // float2 stride between buffers
    const int bufStrU2 = WARPS * 8;    // ulonglong2 stride between buffers

    float4 qa = __ldg(P4);
    float4 qb = __ldg(P4 + 1);

    #pragma unroll 1
    for (int i = 0; i < nb; i++) {
        const int buf = i & 1;

        // ---- Stage A: logits (4 pts), butterfly, exp, STS ----
        {
            const ull px0 = pk2(qa.x,qa.x), py0 = pk2(qa.y,qa.y);
            const ull px1 = pk2(qa.z,qa.z), py1 = pk2(qa.w,qa.w);
            const ull px2 = pk2(qb.x,qb.x), py2 = pk2(qb.y,qb.y);
            const ull px3 = pk2(qb.z,qb.z), py3 = pk2(qb.w,qb.w);

            ull ac0 = 0ull, ac1 = 0ull, ac2 = 0ull, ac3 = 0ull;
            #pragma unroll
            for (int k = 0; k < 4; k++) {
                ac0 = ffma2(relu2(ffma2(py0,bK[k], ffma2(px0,aK[k], cK[k]))), vK[k], ac0);
                ac1 = ffma2(relu2(ffma2(py1,bK[k], ffma2(px1,aK[k], cK[k]))), vK[k], ac1);
                ac2 = ffma2(relu2(ffma2(py2,bK[k], ffma2(px2,aK[k], cK[k]))), vK[k], ac2);
                ac3 = ffma2(relu2(ffma2(py3,bK[k], ffma2(px3,aK[k], cK[k]))), vK[k], ac3);
            }
            float2 t;
            t = upk2(ac0); float a0 = t.x + t.y;
            t = upk2(ac1); float a1 = t.x + t.y;
            t = upk2(ac2); float a2 = t.x + t.y;
            t = upk2(ac3); float a3 = t.x + t.y;

            // batched butterfly over 8 lanes: 4 shfl / 4 points
            const float r0s = __shfl_xor_sync(0xffffffffu, sel1 ? a0 : a2, 1);
            const float r1s = __shfl_xor_sync(0xffffffffu, sel1 ? a1 : a3, 1);
            a0 = (sel1 ? a2 : a0) + r0s;
            a1 = (sel1 ? a3 : a1) + r1s;
            const float r2s = __shfl_xor_sync(0xffffffffu, sel2 ? a0 : a1, 2);
            float v = (sel2 ? a1 : a0) + r2s;
            v += __shfl_xor_sync(0xffffffffu, v, 4);

            const float w = exp2f(fmaf(v, LOG2E, b2l));
            sOwn += w;                          // each (pt,h) counted twice per 8-group
            if (s < 4) wptr[buf * bufStrF2] = make_float2(w, w);
        }

        // ---- prefetch next batch while weights land ----
        float4 na = qa, nb4 = qb;
        if (i + 1 < nb) {
            na  = __ldg(P4 + 2*(i+1));
            nb4 = __ldg(P4 + 2*(i+1) + 1);
        }

        __syncwarp();

        // ---- Stage B: encoder + paired pooling (4 pts) ----
        {
            const ulonglong2* wv = WV + buf * bufStrU2;
            ull h2; ulonglong2 w01, w23;

            h2 = relu2(ffma2(pk2(qa.y,qa.y), e2p, ffma2(pk2(qa.x,qa.x), e1p, bep)));
            w01 = wv[0]; w23 = wv[1];
            P0 = ffma2(w01.x, h2, P0); P1 = ffma2(w01.y, h2, P1);
            P2 = ffma2(w23.x, h2, P2); P3 = ffma2(w23.y, h2, P3);

            h2 = relu2(ffma2(pk2(qa.w,qa.w), e2p, ffma2(pk2(qa.z,qa.z), e1p, bep)));
            w01 = wv[2]; w23 = wv[3];
            P0 = ffma2(w01.x, h2, P0); P1 = ffma2(w01.y, h2, P1);
            P2 = ffma2(w23.x, h2, P2); P3 = ffma2(w23.y, h2, P3);

            h2 = relu2(ffma2(pk2(qb.y,qb.y), e2p, ffma2(pk2(qb.x,qb.x), e1p, bep)));
            w01 = wv[4]; w23 = wv[5];
            P0 = ffma2(w01.x, h2, P0); P1 = ffma2(w01.y, h2, P1);
            P2 = ffma2(w23.x, h2, P2); P3 = ffma2(w23.y, h2, P3);

            h2 = relu2(ffma2(pk2(qb.w,qb.w), e2p, ffma2(pk2(qb.z,qb.z), e1p, bep)));
            w01 = wv[6]; w23 = wv[7];
            P0 = ffma2(w01.x, h2, P0); P1 = ffma2(w01.y, h2, P1);
            P2 = ffma2(w23.x, h2, P2); P3 = ffma2(w23.y, h2, P3);
        }
        qa = na; qb = nb4;
    }

    // ---------------- Per-warp write-back ----------------
    {
        float2 f;
        f = upk2(P0); sRed[warp][0][lane] = f.x; sRed[warp][0][lane+32] = f.y;
        f = upk2(P1); sRed[warp][1][lane] = f.x; sRed[warp][1][lane+32] = f.y;
        f = upk2(P2); sRed[warp][2][lane] = f.x; sRed[warp][2][lane+32] = f.y;
        f = upk2(P3); sRed[warp][3][lane] = f.x; sRed[warp][3][lane+32] = f.y;
    }
    sOwn += __shfl_xor_sync(0xffffffffu, sOwn, 1);
    sOwn += __shfl_xor_sync(0xffffffffu, sOwn, 2);
    sOwn += __shfl_xor_sync(0xffffffffu, sOwn, 4);
    if (s == 0) sWsum[warp][h] = sOwn * 0.5f;   // dedupe the s / s+4 duplication
    __syncthreads();

    // ---------------- Finalize: normalize, @enc_w2, output MLP ----------------
    if (tid < 4) {
        float ss = 0.f;
        #pragma unroll
        for (int w = 0; w < WARPS; w++) ss += sWsum[w][tid];
        sSum[tid] = ss;
    }
    __syncthreads();
    if (tid < 256) {
        const int hh = tid >> 6, j = tid & 63;
        float acc = 0.f;
        #pragma unroll
        for (int w = 0; w < WARPS; w++) acc += sRed[w][hh][j];
        sPooled[hh][j] = acc / sSum[hh];
    }
    __syncthreads();
    if (tid < 256) {
        const int hh = tid >> 6, d = tid & 63;
        float acc = enc_b2[d];
        #pragma unroll 8
        for (int k = 0; k < 64; k++)
            acc = fmaf(sPooled[hh][k], enc_w2[k*64 + d], acc);
        sCtx[hh*64 + d] = acc;     // head-major, matches reshape(B, H*HID)
    }
    __syncthreads();
    if (tid < 64) {
        float acc = out_b1[tid];
        #pragma unroll 8
        for (int c = 0; c < 256; c++)
            acc = fmaf(sCtx[c], out_w1[c*64 + tid], acc);
        sO[tid] = fmaxf(acc, 0.f);
    }
    __syncthreads();
    if (tid < 32) {
        float v = sO[tid]*out_w2[tid] + sO[tid+32]*out_w2[tid+32];
        #pragma unroll
        for (int o = 16; o > 0; o >>= 1)
            v += __shfl_xor_sync(0xffffffffu, v, o);
        if (tid == 0) out[b] = v + out_b2[0];
    }
}

extern "C" void kernel_launch(void* const* d_in, const int* in_sizes, int n_in,
                              void* d_out, int out_size)
{
    const float* radar_xy  = (const float*)d_in[0];
    const float* radar_dir = (const float*)d_in[1];
    const float* pts       = (const float*)d_in[2];
    const float* enc_w1    = (const float*)d_in[3];
    const float* enc_b1    = (const float*)d_in[4];
    const float* enc_w2    = (const float*)d_in[5];
    const float* enc_b2    = (const float*)d_in[6];
    const float* sc_w1     = (const float*)d_in[7];
    const float* sc_b1     = (const float*)d_in[8];
    const float* sc_w2     = (const float*)d_in[9];
    const float* sc_b2     = (const float*)d_in[10];
    const float* out_w1    = (const float*)d_in[11];
    const float* out_b1    = (const float*)d_in[12];
    const float* out_w2    = (const float*)d_in[13];
    const float* out_b2    = (const float*)d_in[14];
    float* out = (float*)d_out;

    mha_fused_kernel<<<Bq, THREADS>>>(
        radar_xy, radar_dir, pts,
        enc_w1, enc_b1, enc_w2, enc_b2,
        sc_w1, sc_b1, sc_w2, sc_b2,
        out_w1, out_b1, out_w2, out_b2,
        out);
}

// round 12
// speedup vs baseline: 1.1750x; 1.1750x over previous
#include <cuda_runtime.h>

// Problem constants (fixed by setup_inputs)
#define Bq      128
#define Nq      8192
#define THREADS 1024
#define WARPS   32
#define PPW     (Nq / WARPS)   // 256 points per warp
#define NBATCH  (PPW / 4)      // 64 batches of 4 points

#define LOG2E 1.4426950408889634f

typedef unsigned long long ull;

// ---- Blackwell packed fp32x2 helpers (FFMA2 only reachable via PTX) ----
static __device__ __forceinline__ ull pk2(float lo, float hi) {
    ull r; asm("mov.b64 %0, {%1, %2};" : "=l"(r) : "f"(lo), "f"(hi)); return r;
}
static __device__ __forceinline__ ull ffma2(ull a, ull b, ull c) {
    ull d; asm("fma.rn.f32x2 %0, %1, %2, %3;" : "=l"(d) : "l"(a), "l"(b), "l"(c)); return d;
}
static __device__ __forceinline__ float2 upk2(ull v) {
    float2 f; asm("mov.b64 {%0, %1}, %2;" : "=f"(f.x), "=f"(f.y) : "l"(v)); return f;
}
static __device__ __forceinline__ ull relu2(ull v) {
    float2 f = upk2(v);
    return pk2(fmaxf(f.x, 0.f), fmaxf(f.y, 0.f));
}

__global__ __launch_bounds__(THREADS, 1)
void mha_fused_kernel(const float* __restrict__ radar_xy,
                      const float* __restrict__ radar_dir,
                      const float* __restrict__ pts,
                      const float* __restrict__ enc_w1,
                      const float* __restrict__ enc_b1,
                      const float* __restrict__ enc_w2,
                      const float* __restrict__ enc_b2,
                      const float* __restrict__ sc_w1,
                      const float* __restrict__ sc_b1,
                      const float* __restrict__ sc_w2,
                      const float* __restrict__ sc_b2,
                      const float* __restrict__ out_w1,
                      const float* __restrict__ out_b1,
                      const float* __restrict__ out_w2,
                      const float* __restrict__ out_b2,
                      float* __restrict__ out)
{
    __shared__ ulonglong2 sAB[4][32];    // (a-pair px, b-pair py) per (k, lane) — read once to regs
    __shared__ ulonglong2 sC2[2][32];    // per-batch bias c-pairs: [0]=(cK0,cK1), [1]=(cK2,cK3) — in-loop
    __shared__ ulonglong2 sV2[2][32];    // score-w2 v-pairs — read once to regs
    __shared__ ull        sE1p[32], sE2p[32], sBEp[32];
    // Softmax weights as duplicated pairs; per (buf,warp): 8 float4 = [pt][h-pair]
    __shared__ float4     sWexp[2][WARPS][8];
    __shared__ float      sRed[WARPS][4][64];
    __shared__ float      sWsum[WARPS][4];
    __shared__ float      sSum[4];
    __shared__ float      sPooled[4][64];
    __shared__ float      sCtx[256];
    __shared__ float      sO[64];

    const int b    = blockIdx.x;
    const int tid  = threadIdx.x;
    const int warp = tid >> 5;
    const int lane = tid & 31;

    const float r0 = radar_xy[b*2+0], r1 = radar_xy[b*2+1];
    const float r2 = radar_dir[b*2+0], r3 = radar_dir[b*2+1];

    // ---------------- Staging ----------------
    if (tid < 128) {
        const int k = tid >> 5, hs = tid & 31;
        const int hh = hs >> 3, j = (hs & 7) * 8 + k * 2;
        const float* w = sc_w1 + (size_t)hh * 384;
        ulonglong2 ab;
        ab.x = pk2(w[256+j], w[256+j+1]);   // row 4: px coeffs
        ab.y = pk2(w[320+j], w[320+j+1]);   // row 5: py coeffs
        sAB[k][hs] = ab;
    } else if (tid < 192) {
        // c-pairs: k2 in {0,1}; covers k = 2*k2, 2*k2+1 -> j0 = (hs&7)*8 + 4*k2, 4 values
        const int idx = tid - 128, k2 = idx >> 5, hs = idx & 31;
        const int hh = hs >> 3, j0 = (hs & 7) * 8 + k2 * 4;
        const float* w = sc_w1 + (size_t)hh * 384;
        float c[4];
        #pragma unroll
        for (int t = 0; t < 4; t++) {
            const int j = j0 + t;
            c[t] = sc_b1[hh*64+j] + r0*w[j] + r1*w[64+j] + r2*w[128+j] + r3*w[192+j];
        }
        ulonglong2 cc; cc.x = pk2(c[0], c[1]); cc.y = pk2(c[2], c[3]);
        sC2[k2][hs] = cc;
    } else if (tid < 256) {
        const int idx = tid - 192, k2 = idx >> 5, hs = idx & 31;
        const int hh = hs >> 3, j0 = (hs & 7) * 8 + k2 * 4;
        ulonglong2 vv;
        vv.x = pk2(sc_w2[hh*64+j0],   sc_w2[hh*64+j0+1]);
        vv.y = pk2(sc_w2[hh*64+j0+2], sc_w2[hh*64+j0+3]);
        sV2[k2][hs] = vv;
    } else if (tid < 352) {
        const int idx = tid - 256, arr = idx >> 5, l = idx & 31;
        if (arr == 0)      sE1p[l] = pk2(enc_w1[256+l], enc_w1[256+l+32]);
        else if (arr == 1) sE2p[l] = pk2(enc_w1[320+l], enc_w1[320+l+32]);
        else {
            const float b0 = enc_b1[l]    + r0*enc_w1[l]     + r1*enc_w1[64+l]
                                          + r2*enc_w1[128+l]  + r3*enc_w1[192+l];
            const float b1 = enc_b1[l+32] + r0*enc_w1[l+32]  + r1*enc_w1[64+l+32]
                                          + r2*enc_w1[128+l+32] + r3*enc_w1[192+l+32];
            sBEp[l] = pk2(b0, b1);
        }
    }
    __syncthreads();

    // ---------------- Per-lane constants ----------------
    const int h = lane >> 3, s = lane & 7;
    const float b2l = sc_b2[h] * LOG2E;
    // After the butterfly, lane s holds point p(s) = (s&1)*2 + ((s>>1)&1)
    const int pOwn = ((s & 1) << 1) + ((s >> 1) & 1);
    const bool sel1 = (s & 1) != 0, sel2 = (s & 2) != 0;

    // Register-resident weights: a,b (16 regs) + v (8 regs); c reloaded per iter (2 LDS.128)
    ull aK[4], bK[4], vK[4];
    #pragma unroll
    for (int k = 0; k < 4; k++) {
        ulonglong2 t = sAB[k][lane]; aK[k] = t.x; bK[k] = t.y;
    }
    {
        ulonglong2 v01 = sV2[0][lane]; vK[0] = v01.x; vK[1] = v01.y;
        ulonglong2 v23 = sV2[1][lane]; vK[2] = v23.x; vK[3] = v23.y;
    }
    const ull e1p = sE1p[lane], e2p = sE2p[lane], bep = sBEp[lane];

    ull P0 = 0ull, P1 = 0ull, P2 = 0ull, P3 = 0ull;   // pooled (feat lane, lane+32) x 4 heads
    float sOwn = 0.f;

    const float4* P4 = reinterpret_cast<const float4*>(pts)
                     + (((size_t)b * Nq + (size_t)warp * PPW) >> 1);

    float2* wptr = reinterpret_cast<float2*>(
        reinterpret_cast<float*>(&sWexp[0][warp][0]) + pOwn * 8 + h * 2);
    const ulonglong2* WV = reinterpret_cast<const ulonglong2*>(&sWexp[0][warp][0]);
    const int bufStrF2 = WARPS * 16;   // float2 stride between buffers
    const int bufStrU2 = WARPS * 8;    // ulonglong2 stride between buffers

    #pragma unroll 2
    for (int i = 0; i < NBATCH; i++) {
        const int buf = i & 1;
        const float4 qa = __ldg(P4 + 2*i);
        const float4 qb = __ldg(P4 + 2*i + 1);

        // ---- Stage A: logits (4 pts), butterfly, exp, STS ----
        {
            const ull px0 = pk2(qa.x,qa.x), py0 = pk2(qa.y,qa.y);
            const ull px1 = pk2(qa.z,qa.z), py1 = pk2(qa.w,qa.w);
            const ull px2 = pk2(qb.x,qb.x), py2 = pk2(qb.y,qb.y);
            const ull px3 = pk2(qb.z,qb.z), py3 = pk2(qb.w,qb.w);

            const ulonglong2 c01 = sC2[0][lane];   // cK0, cK1
            const ulonglong2 c23 = sC2[1][lane];   // cK2, cK3

            ull ac0, ac1, ac2, ac3;
            ac0 = ffma2(relu2(ffma2(py0,bK[0], ffma2(px0,aK[0], c01.x))), vK[0], 0ull);
            ac1 = ffma2(relu2(ffma2(py1,bK[0], ffma2(px1,aK[0], c01.x))), vK[0], 0ull);
            ac2 = ffma2(relu2(ffma2(py2,bK[0], ffma2(px2,aK[0], c01.x))), vK[0], 0ull);
            ac3 = ffma2(relu2(ffma2(py3,bK[0], ffma2(px3,aK[0], c01.x))), vK[0], 0ull);
            ac0 = ffma2(relu2(ffma2(py0,bK[1], ffma2(px0,aK[1], c01.y))), vK[1], ac0);
            ac1 = ffma2(relu2(ffma2(py1,bK[1], ffma2(px1,aK[1], c01.y))), vK[1], ac1);
            ac2 = ffma2(relu2(ffma2(py2,bK[1], ffma2(px2,aK[1], c01.y))), vK[1], ac2);
            ac3 = ffma2(relu2(ffma2(py3,bK[1], ffma2(px3,aK[1], c01.y))), vK[1], ac3);
            ac0 = ffma2(relu2(ffma2(py0,bK[2], ffma2(px0,aK[2], c23.x))), vK[2], ac0);
            ac1 = ffma2(relu2(ffma2(py1,bK[2], ffma2(px1,aK[2], c23.x))), vK[2], ac1);
            ac2 = ffma2(relu2(ffma2(py2,bK[2], ffma2(px2,aK[2], c23.x))), vK[2], ac2);
            ac3 = ffma2(relu2(ffma2(py3,bK[2], ffma2(px3,aK[2], c23.x))), vK[2], ac3);
            ac0 = ffma2(relu2(ffma2(py0,bK[3], ffma2(px0,aK[3], c23.y))), vK[3], ac0);
            ac1 = ffma2(relu2(ffma2(py1,bK[3], ffma2(px1,aK[3], c23.y))), vK[3], ac1);
            ac2 = ffma2(relu2(ffma2(py2,bK[3], ffma2(px2,aK[3], c23.y))), vK[3], ac2);
            ac3 = ffma2(relu2(ffma2(py3,bK[3], ffma2(px3,aK[3], c23.y))), vK[3], ac3);

            float2 t;
            t = upk2(ac0); float a0 = t.x + t.y;
            t = upk2(ac1); float a1 = t.x + t.y;
            t = upk2(ac2); float a2 = t.x + t.y;
            t = upk2(ac3); float a3 = t.x + t.y;

            // batched butterfly over 8 lanes: 4 shfl / 4 points
            const float r0s = __shfl_xor_sync(0xffffffffu, sel1 ? a0 : a2, 1);
            const float r1s = __shfl_xor_sync(0xffffffffu, sel1 ? a1 : a3, 1);
            a0 = (sel1 ? a2 : a0) + r0s;
            a1 = (sel1 ? a3 : a1) + r1s;
            const float r2s = __shfl_xor_sync(0xffffffffu, sel2 ? a0 : a1, 2);
            float v = (sel2 ? a1 : a0) + r2s;
            v += __shfl_xor_sync(0xffffffffu, v, 4);

            const float w = exp2f(fmaf(v, LOG2E, b2l));
            sOwn += w;                          // each (pt,h) counted twice per 8-group
            if (s < 4) wptr[buf * bufStrF2] = make_float2(w, w);
        }

        __syncwarp();

        // ---- Stage B: encoder + paired pooling (4 pts) ----
        {
            const ulonglong2* wv = WV + buf * bufStrU2;
            ull h2; ulonglong2 w01, w23;

            h2 = relu2(ffma2(pk2(qa.y,qa.y), e2p, ffma2(pk2(qa.x,qa.x), e1p, bep)));
            w01 = wv[0]; w23 = wv[1];
            P0 = ffma2(w01.x, h2, P0); P1 = ffma2(w01.y, h2, P1);
            P2 = ffma2(w23.x, h2, P2); P3 = ffma2(w23.y, h2, P3);

            h2 = relu2(ffma2(pk2(qa.w,qa.w), e2p, ffma2(pk2(qa.z,qa.z), e1p, bep)));
            w01 = wv[2]; w23 = wv[3];
            P0 = ffma2(w01.x, h2, P0); P1 = ffma2(w01.y, h2, P1);
            P2 = ffma2(w23.x, h2, P2); P3 = ffma2(w23.y, h2, P3);

            h2 = relu2(ffma2(pk2(qb.y,qb.y), e2p, ffma2(pk2(qb.x,qb.x), e1p, bep)));
            w01 = wv[4]; w23 = wv[5];
            P0 = ffma2(w01.x, h2, P0); P1 = ffma2(w01.y, h2, P1);
            P2 = ffma2(w23.x, h2, P2); P3 = ffma2(w23.y, h2, P3);

            h2 = relu2(ffma2(pk2(qb.w,qb.w), e2p, ffma2(pk2(qb.z,qb.z), e1p, bep)));
            w01 = wv[6]; w23 = wv[7];
            P0 = ffma2(w01.x, h2, P0); P1 = ffma2(w01.y, h2, P1);
            P2 = ffma2(w23.x, h2, P2); P3 = ffma2(w23.y, h2, P3);
        }

        __syncwarp();   // protect buf from next-next iteration's STS
    }

    // ---------------- Per-warp write-back ----------------
    {
        float2 f;
        f = upk2(P0); sRed[warp][0][lane] = f.x; sRed[warp][0][lane+32] = f.y;
        f = upk2(P1); sRed[warp][1][lane] = f.x; sRed[warp][1][lane+32] = f.y;
        f = upk2(P2); sRed[warp][2][lane] = f.x; sRed[warp][2][lane+32] = f.y;
        f = upk2(P3); sRed[warp][3][lane] = f.x; sRed[warp][3][lane+32] = f.y;
    }
    sOwn += __shfl_xor_sync(0xffffffffu, sOwn, 1);
    sOwn += __shfl_xor_sync(0xffffffffu, sOwn, 2);
    sOwn += __shfl_xor_sync(0xffffffffu, sOwn, 4);
    if (s == 0) sWsum[warp][h] = sOwn * 0.5f;   // dedupe the s / s+4 duplication
    __syncthreads();

    // ---------------- Finalize: normalize, @enc_w2, output MLP ----------------
    if (tid < 4) {
        float ss = 0.f;
        #pragma unroll
        for (int w = 0; w < WARPS; w++) ss += sWsum[w][tid];
        sSum[tid] = ss;
    }
    __syncthreads();
    if (tid < 256) {
        const int hh = tid >> 6, j = tid & 63;
        float acc = 0.f;
        #pragma unroll
        for (int w = 0; w < WARPS; w++) acc += sRed[w][hh][j];
        sPooled[hh][j] = acc / sSum[hh];
    }
    __syncthreads();
    if (tid < 256) {
        const int hh = tid >> 6, d = tid & 63;
        float acc = enc_b2[d];
        #pragma unroll 8
        for (int k = 0; k < 64; k++)
            acc = fmaf(sPooled[hh][k], enc_w2[k*64 + d], acc);
        sCtx[hh*64 + d] = acc;     // head-major, matches reshape(B, H*HID)
    }
    __syncthreads();
    if (tid < 64) {
        float acc = out_b1[tid];
        #pragma unroll 8
        for (int c = 0; c < 256; c++)
            acc = fmaf(sCtx[c], out_w1[c*64 + tid], acc);
        sO[tid] = fmaxf(acc, 0.f);
    }
    __syncthreads();
    if (tid < 32) {
        float v = sO[tid]*out_w2[tid] + sO[tid+32]*out_w2[tid+32];
        #pragma unroll
        for (int o = 16; o > 0; o >>= 1)
            v += __shfl_xor_sync(0xffffffffu, v, o);
        if (tid == 0) out[b] = v + out_b2[0];
    }
}

extern "C" void kernel_launch(void* const* d_in, const int* in_sizes, int n_in,
                              void* d_out, int out_size)
{
    const float* radar_xy  = (const float*)d_in[0];
    const float* radar_dir = (const float*)d_in[1];
    const float* pts       = (const float*)d_in[2];
    const float* enc_w1    = (const float*)d_in[3];
    const float* enc_b1    = (const float*)d_in[4];
    const float* enc_w2    = (const float*)d_in[5];
    const float* enc_b2    = (const float*)d_in[6];
    const float* sc_w1     = (const float*)d_in[7];
    const float* sc_b1     = (const float*)d_in[8];
    const float* sc_w2     = (const float*)d_in[9];
    const float* sc_b2     = (const float*)d_in[10];
    const float* out_w1    = (const float*)d_in[11];
    const float* out_b1    = (const float*)d_in[12];
    const float* out_w2    = (const float*)d_in[13];
    const float* out_b2    = (const float*)d_in[14];
    float* out = (float*)d_out;

    mha_fused_kernel<<<Bq, THREADS>>>(
        radar_xy, radar_dir, pts,
        enc_w1, enc_b1, enc_w2, enc_b2,
        sc_w1, sc_b1, sc_w2, sc_b2,
        out_w1, out_b1, out_w2, out_b2,
        out);
}

// round 13
// speedup vs baseline: 1.4062x; 1.1968x over previous
#include <cuda_runtime.h>

// Problem constants (fixed by setup_inputs)
#define Bq      128
#define Nq      8192
#define THREADS 1024
#define WARPS   32
#define PPW     (Nq / WARPS)   // 256 points per warp
#define NBATCH  (PPW / 4)      // 64 batches of 4 points

#define LOG2E 1.4426950408889634f

typedef unsigned long long ull;

// ---- Blackwell packed fp32x2 helpers (FFMA2 only reachable via PTX) ----
static __device__ __forceinline__ ull pk2(float lo, float hi) {
    ull r; asm("mov.b64 %0, {%1, %2};" : "=l"(r) : "f"(lo), "f"(hi)); return r;
}
static __device__ __forceinline__ ull ffma2(ull a, ull b, ull c) {
    ull d; asm("fma.rn.f32x2 %0, %1, %2, %3;" : "=l"(d) : "l"(a), "l"(b), "l"(c)); return d;
}
static __device__ __forceinline__ float2 upk2(ull v) {
    float2 f; asm("mov.b64 {%0, %1}, %2;" : "=f"(f.x), "=f"(f.y) : "l"(v)); return f;
}
static __device__ __forceinline__ ull relu2(ull v) {
    float2 f = upk2(v);
    return pk2(fmaxf(f.x, 0.f), fmaxf(f.y, 0.f));
}

__global__ __launch_bounds__(THREADS, 1)
void mha_fused_kernel(const float* __restrict__ radar_xy,
                      const float* __restrict__ radar_dir,
                      const float* __restrict__ pts,
                      const float* __restrict__ enc_w1,
                      const float* __restrict__ enc_b1,
                      const float* __restrict__ enc_w2,
                      const float* __restrict__ enc_b2,
                      const float* __restrict__ sc_w1,
                      const float* __restrict__ sc_b1,
                      const float* __restrict__ sc_w2,
                      const float* __restrict__ sc_b2,
                      const float* __restrict__ out_w1,
                      const float* __restrict__ out_b1,
                      const float* __restrict__ out_w2,
                      const float* __restrict__ out_b2,
                      float* __restrict__ out)
{
    // Score-net weights packed per (k, lane=h*8+s)
    __shared__ ulonglong2 sAB[4][32];                // (a-pair px, b-pair py) — read once to regs
    __shared__ ulonglong2 sCV[4][32];                // (c-pair bias, v-pair w2) — 4 LDS.128 in-loop (R9 form)
    __shared__ ull        sE1p[32], sE2p[32], sBEp[32];  // encoder packed (j, j+32)
    // Softmax weights as duplicated pairs; per (buf,warp): 8 float4 = [pt][(h0,h0,h1,h1)|(h2,h2,h3,h3)]
    __shared__ float4     sWexp[2][WARPS][8];
    __shared__ float      sRed[WARPS][4][64];        // per-warp pooled partials
    __shared__ float      sWsum[WARPS][4];
    __shared__ float      sSum[4];
    __shared__ float      sPooled[4][64];
    __shared__ float      sCtx[256];
    __shared__ float      sO[64];

    const int b    = blockIdx.x;
    const int tid  = threadIdx.x;
    const int warp = tid >> 5;
    const int lane = tid & 31;

    const float r0 = radar_xy[b*2+0], r1 = radar_xy[b*2+1];
    const float r2 = radar_dir[b*2+0], r3 = radar_dir[b*2+1];

    // ---------------- Staging (identical to R9) ----------------
    if (tid < 128) {
        const int k = tid >> 5, hs = tid & 31;
        const int hh = hs >> 3, j = (hs & 7) * 8 + k * 2;
        const float* w = sc_w1 + (size_t)hh * 384;
        const float c0 = sc_b1[hh*64+j]   + r0*w[j]   + r1*w[64+j]   + r2*w[128+j]   + r3*w[192+j];
        const float c1 = sc_b1[hh*64+j+1] + r0*w[j+1] + r1*w[64+j+1] + r2*w[128+j+1] + r3*w[192+j+1];
        ulonglong2 cv;
        cv.x = pk2(c0, c1);
        cv.y = pk2(sc_w2[hh*64+j], sc_w2[hh*64+j+1]);
        sCV[k][hs] = cv;
    } else if (tid < 224) {
        const int idx = tid - 128, arr = idx >> 5, l = idx & 31;
        if (arr == 0)      sE1p[l] = pk2(enc_w1[256+l], enc_w1[256+l+32]);
        else if (arr == 1) sE2p[l] = pk2(enc_w1[320+l], enc_w1[320+l+32]);
        else {
            const float b0 = enc_b1[l]    + r0*enc_w1[l]     + r1*enc_w1[64+l]
                                          + r2*enc_w1[128+l]  + r3*enc_w1[192+l];
            const float b1 = enc_b1[l+32] + r0*enc_w1[l+32]  + r1*enc_w1[64+l+32]
                                          + r2*enc_w1[128+l+32] + r3*enc_w1[192+l+32];
            sBEp[l] = pk2(b0, b1);
        }
    } else if (tid >= 256 && tid < 384) {
        const int idx = tid - 256;
        const int k = idx >> 5, hs = idx & 31;
        const int hh = hs >> 3, j = (hs & 7) * 8 + k * 2;
        const float* w = sc_w1 + (size_t)hh * 384;
        ulonglong2 ab;
        ab.x = pk2(w[256+j], w[256+j+1]);   // row 4: px coeffs
        ab.y = pk2(w[320+j], w[320+j+1]);   // row 5: py coeffs
        sAB[k][hs] = ab;
    }
    __syncthreads();

    // ---------------- Per-lane constants (R9 register budget) ----------------
    const int h = lane >> 3, s = lane & 7;
    const float b2l = sc_b2[h] * LOG2E;
    // After the butterfly, lane s holds point p(s) = (s&1)*2 + ((s>>1)&1)
    const int pOwn = ((s & 1) << 1) + ((s >> 1) & 1);
    const bool sel1 = (s & 1) != 0, sel2 = (s & 2) != 0;

    ull aK[4], bK[4];
    #pragma unroll
    for (int k = 0; k < 4; k++) {
        ulonglong2 t = sAB[k][lane]; aK[k] = t.x; bK[k] = t.y;
    }
    const ull e1p = sE1p[lane], e2p = sE2p[lane], bep = sBEp[lane];

    ull P0 = 0ull, P1 = 0ull, P2 = 0ull, P3 = 0ull;   // pooled (feat lane, lane+32) x 4 heads
    float sOwn = 0.f;

    const float4* P4 = reinterpret_cast<const float4*>(pts)
                     + (((size_t)b * Nq + (size_t)warp * PPW) >> 1);

    float2* wptr = reinterpret_cast<float2*>(
        reinterpret_cast<float*>(&sWexp[0][warp][0]) + pOwn * 8 + h * 2);
    const ulonglong2* WV = reinterpret_cast<const ulonglong2*>(&sWexp[0][warp][0]);
    const int bufStrF2 = WARPS * 16;   // float2 stride between buffers
    const int bufStrU2 = WARPS * 8;    // ulonglong2 stride between buffers

    #pragma unroll 2
    for (int i = 0; i < NBATCH; i++) {
        const int buf = i & 1;
        const float4 qa = __ldg(P4 + 2*i);
        const float4 qb = __ldg(P4 + 2*i + 1);

        // ---- Stage A: logits (4 pts), butterfly, exp, STS (exact R9 form) ----
        {
            const ull px0 = pk2(qa.x,qa.x), py0 = pk2(qa.y,qa.y);
            const ull px1 = pk2(qa.z,qa.z), py1 = pk2(qa.w,qa.w);
            const ull px2 = pk2(qb.x,qb.x), py2 = pk2(qb.y,qb.y);
            const ull px3 = pk2(qb.z,qb.z), py3 = pk2(qb.w,qb.w);

            ull ac0, ac1, ac2, ac3;
            {
                ulonglong2 cv = sCV[0][lane];
                ac0 = ffma2(relu2(ffma2(py0,bK[0], ffma2(px0,aK[0], cv.x))), cv.y, 0ull);
                ac1 = ffma2(relu2(ffma2(py1,bK[0], ffma2(px1,aK[0], cv.x))), cv.y, 0ull);
                ac2 = ffma2(relu2(ffma2(py2,bK[0], ffma2(px2,aK[0], cv.x))), cv.y, 0ull);
                ac3 = ffma2(relu2(ffma2(py3,bK[0], ffma2(px3,aK[0], cv.x))), cv.y, 0ull);
                cv = sCV[1][lane];
                ac0 = ffma2(relu2(ffma2(py0,bK[1], ffma2(px0,aK[1], cv.x))), cv.y, ac0);
                ac1 = ffma2(relu2(ffma2(py1,bK[1], ffma2(px1,aK[1], cv.x))), cv.y, ac1);
                ac2 = ffma2(relu2(ffma2(py2,bK[1], ffma2(px2,aK[1], cv.x))), cv.y, ac2);
                ac3 = ffma2(relu2(ffma2(py3,bK[1], ffma2(px3,aK[1], cv.x))), cv.y, ac3);
                cv = sCV[2][lane];
                ac0 = ffma2(relu2(ffma2(py0,bK[2], ffma2(px0,aK[2], cv.x))), cv.y, ac0);
                ac1 = ffma2(relu2(ffma2(py1,bK[2], ffma2(px1,aK[2], cv.x))), cv.y, ac1);
                ac2 = ffma2(relu2(ffma2(py2,bK[2], ffma2(px2,aK[2], cv.x))), cv.y, ac2);
                ac3 = ffma2(relu2(ffma2(py3,bK[2], ffma2(px3,aK[2], cv.x))), cv.y, ac3);
                cv = sCV[3][lane];
                ac0 = ffma2(relu2(ffma2(py0,bK[3], ffma2(px0,aK[3], cv.x))), cv.y, ac0);
                ac1 = ffma2(relu2(ffma2(py1,bK[3], ffma2(px1,aK[3], cv.x))), cv.y, ac1);
                ac2 = ffma2(relu2(ffma2(py2,bK[3], ffma2(px2,aK[3], cv.x))), cv.y, ac2);
                ac3 = ffma2(relu2(ffma2(py3,bK[3], ffma2(px3,aK[3], cv.x))), cv.y, ac3);
            }
            float2 t;
            t = upk2(ac0); float a0 = t.x + t.y;
            t = upk2(ac1); float a1 = t.x + t.y;
            t = upk2(ac2); float a2 = t.x + t.y;
            t = upk2(ac3); float a3 = t.x + t.y;

            // batched butterfly over 8 lanes: 4 shfl / 4 points
            const float r0s = __shfl_xor_sync(0xffffffffu, sel1 ? a0 : a2, 1);
            const float r1s = __shfl_xor_sync(0xffffffffu, sel1 ? a1 : a3, 1);
            a0 = (sel1 ? a2 : a0) + r0s;
            a1 = (sel1 ? a3 : a1) + r1s;
            const float r2s = __shfl_xor_sync(0xffffffffu, sel2 ? a0 : a1, 2);
            float v = (sel2 ? a1 : a0) + r2s;
            v += __shfl_xor_sync(0xffffffffu, v, 4);

            const float w = exp2f(fmaf(v, LOG2E, b2l));
            sOwn += w;                          // each (pt,h) counted twice per 8-group
            if (s < 4) wptr[buf * bufStrF2] = make_float2(w, w);
        }

        __syncwarp();   // single sync: 2 buffers make STS(i+1) vs LDS(i) race-free

        // ---- Stage B: encoder + paired pooling (4 pts), packed FFMA2 ----
        {
            const ulonglong2* wv = WV + buf * bufStrU2;
            ull h2; ulonglong2 w01, w23;

            h2 = relu2(ffma2(pk2(qa.y,qa.y), e2p, ffma2(pk2(qa.x,qa.x), e1p, bep)));
            w01 = wv[0]; w23 = wv[1];
            P0 = ffma2(w01.x, h2, P0); P1 = ffma2(w01.y, h2, P1);
            P2 = ffma2(w23.x, h2, P2); P3 = ffma2(w23.y, h2, P3);

            h2 = relu2(ffma2(pk2(qa.w,qa.w), e2p, ffma2(pk2(qa.z,qa.z), e1p, bep)));
            w01 = wv[2]; w23 = wv[3];
            P0 = ffma2(w01.x, h2, P0); P1 = ffma2(w01.y, h2, P1);
            P2 = ffma2(w23.x, h2, P2); P3 = ffma2(w23.y, h2, P3);

            h2 = relu2(ffma2(pk2(qb.y,qb.y), e2p, ffma2(pk2(qb.x,qb.x), e1p, bep)));
            w01 = wv[4]; w23 = wv[5];
            P0 = ffma2(w01.x, h2, P0); P1 = ffma2(w01.y, h2, P1);
            P2 = ffma2(w23.x, h2, P2); P3 = ffma2(w23.y, h2, P3);

            h2 = relu2(ffma2(pk2(qb.w,qb.w), e2p, ffma2(pk2(qb.z,qb.z), e1p, bep)));
            w01 = wv[6]; w23 = wv[7];
            P0 = ffma2(w01.x, h2, P0); P1 = ffma2(w01.y, h2, P1);
            P2 = ffma2(w23.x, h2, P2); P3 = ffma2(w23.y, h2, P3);
        }
    }

    // ---------------- Per-warp write-back ----------------
    {
        float2 f;
        f = upk2(P0); sRed[warp][0][lane] = f.x; sRed[warp][0][lane+32] = f.y;
        f = upk2(P1); sRed[warp][1][lane] = f.x; sRed[warp][1][lane+32] = f.y;
        f = upk2(P2); sRed[warp][2][lane] = f.x; sRed[warp][2][lane+32] = f.y;
        f = upk2(P3); sRed[warp][3][lane] = f.x; sRed[warp][3][lane+32] = f.y;
    }
    sOwn += __shfl_xor_sync(0xffffffffu, sOwn, 1);
    sOwn += __shfl_xor_sync(0xffffffffu, sOwn, 2);
    sOwn += __shfl_xor_sync(0xffffffffu, sOwn, 4);
    if (s == 0) sWsum[warp][h] = sOwn * 0.5f;   // dedupe the s / s+4 duplication
    __syncthreads();

    // ---------------- Finalize: normalize, @enc_w2, output MLP ----------------
    if (tid < 4) {
        float ss = 0.f;
        #pragma unroll
        for (int w = 0; w < WARPS; w++) ss += sWsum[w][tid];
        sSum[tid] = ss;
    }
    __syncthreads();
    if (tid < 256) {
        const int hh = tid >> 6, j = tid & 63;
        float acc = 0.f;
        #pragma unroll
        for (int w = 0; w < WARPS; w++) acc += sRed[w][hh][j];
        sPooled[hh][j] = acc / sSum[hh];
    }
    __syncthreads();
    if (tid < 256) {
        const int hh = tid >> 6, d = tid & 63;
        float acc = enc_b2[d];
        #pragma unroll 8
        for (int k = 0; k < 64; k++)
            acc = fmaf(sPooled[hh][k], enc_w2[k*64 + d], acc);
        sCtx[hh*64 + d] = acc;     // head-major, matches reshape(B, H*HID)
    }
    __syncthreads();
    if (tid < 64) {
        float acc = out_b1[tid];
        #pragma unroll 8
        for (int c = 0; c < 256; c++)
            acc = fmaf(sCtx[c], out_w1[c*64 + tid], acc);
        sO[tid] = fmaxf(acc, 0.f);
    }
    __syncthreads();
    if (tid < 32) {
        float v = sO[tid]*out_w2[tid] + sO[tid+32]*out_w2[tid+32];
        #pragma unroll
        for (int o = 16; o > 0; o >>= 1)
            v += __shfl_xor_sync(0xffffffffu, v, o);
        if (tid == 0) out[b] = v + out_b2[0];
    }
}

extern "C" void kernel_launch(void* const* d_in, const int* in_sizes, int n_in,
                              void* d_out, int out_size)
{
    const float* radar_xy  = (const float*)d_in[0];
    const float* radar_dir = (const float*)d_in[1];
    const float* pts       = (const float*)d_in[2];
    const float* enc_w1    = (const float*)d_in[3];
    const float* enc_b1    = (const float*)d_in[4];
    const float* enc_w2    = (const float*)d_in[5];
    const float* enc_b2    = (const float*)d_in[6];
    const float* sc_w1     = (const float*)d_in[7];
    const float* sc_b1     = (const float*)d_in[8];
    const float* sc_w2     = (const float*)d_in[9];
    const float* sc_b2     = (const float*)d_in[10];
    const float* out_w1    = (const float*)d_in[11];
    const float* out_b1    = (const float*)d_in[12];
    const float* out_w2    = (const float*)d_in[13];
    const float* out_b2    = (const float*)d_in[14];
    float* out = (float*)d_out;

    mha_fused_kernel<<<Bq, THREADS>>>(
        radar_xy, radar_dir, pts,
        enc_w1, enc_b1, enc_w2, enc_b2,
        sc_w1, sc_b1, sc_w2, sc_b2,
        out_w1, out_b1, out_w2, out_b2,
        out);
}